// round 5
// baseline (speedup 1.0000x reference)
#include <cuda_runtime.h>
#include <cstdint>

// Problem constants
#define BB   16
#define CC   128
#define C4C  32
#define NPIX 2304                      // H*W = 48*48
#define NT   18                        // NPIX / 128
#define BN_EPS 1e-5f

// -------- scratch (device globals; no allocation allowed) --------
__device__ float g_K [BB * C4C * NPIX];          // [b][k][n]
__device__ float g_QT[BB * NPIX * C4C];          // [b][m][k]  (Q transposed)
__device__ float g_V [BB * CC  * NPIX];          // [b][c][m]
__device__ float g_pZ[BB * NT];
__device__ float g_M [BB];

// -------- packed f32x2 helpers --------
__device__ __forceinline__ unsigned long long pk2(float lo, float hi) {
    unsigned long long r;
    asm("mov.b64 %0, {%1,%2};" : "=l"(r) : "f"(lo), "f"(hi));
    return r;
}
__device__ __forceinline__ float2 up2(unsigned long long v) {
    float2 r;
    asm("mov.b64 {%0,%1}, %2;" : "=f"(r.x), "=f"(r.y) : "l"(v));
    return r;
}
__device__ __forceinline__ void fma2(unsigned long long& d,
                                     unsigned long long a,
                                     unsigned long long b) {
    asm("fma.rn.f32x2 %0, %1, %2, %0;" : "+l"(d) : "l"(a), "l"(b));
}
__device__ __forceinline__ uint32_t smem_to_u32(const void* p) {
    uint32_t a;
    asm("{ .reg .u64 t; cvta.to.shared.u64 t, %1; cvt.u32.u64 %0, t; }"
        : "=r"(a) : "l"(p));
    return a;
}
__device__ __forceinline__ void cp16(uint32_t dst, const void* src) {
    asm volatile("cp.async.cg.shared.global [%0], [%1], 16;"
                 :: "r"(dst), "l"(src) : "memory");
}
#define CP_COMMIT() asm volatile("cp.async.commit_group;" ::: "memory")
#define CP_WAIT0()  asm volatile("cp.async.wait_group 0;" ::: "memory")

// warp-level tf32 MMA: D[16x8] += A[16x8] * B[8x8]
__device__ __forceinline__ void mma16n8k8(float* d, const uint32_t* a,
                                          const uint32_t* b) {
    asm volatile(
        "mma.sync.aligned.m16n8k8.row.col.f32.tf32.tf32.f32 "
        "{%0,%1,%2,%3}, {%4,%5,%6,%7}, {%8,%9}, {%0,%1,%2,%3};"
        : "+f"(d[0]), "+f"(d[1]), "+f"(d[2]), "+f"(d[3])
        : "r"(a[0]), "r"(a[1]), "r"(a[2]), "r"(a[3]), "r"(b[0]), "r"(b[1]));
}

// ============================================================================
// conv128: Y[b,o,n] = relu( sum_c Wf[o,c]*X[b,c,n] + bias[o] ),  O = 128
// ============================================================================
__global__ void __launch_bounds__(256) conv128_kernel(
    const float* __restrict__ X, size_t xStride, int CIN,
    const float* __restrict__ W,
    const float* __restrict__ gam, const float* __restrict__ bet,
    const float* __restrict__ mean, const float* __restrict__ var,
    float* __restrict__ Y, size_t yStride)
{
    __shared__ __align__(16) float Ws[16][128];
    __shared__ __align__(16) float Xs[16][128];
    __shared__ float scale_s[128], bias_s[128];

    const int t  = threadIdx.x;
    const int b  = blockIdx.y;
    const int n0 = blockIdx.x * 128;

    if (t < 128) {
        float s = gam[t] * rsqrtf(var[t] + BN_EPS);
        scale_s[t] = s;
        bias_s[t]  = bet[t] - mean[t] * s;
    }
    __syncthreads();

    const float* Xb = X + (size_t)b * xStride + n0;
    const int ty = t >> 4, tx = t & 15;

    unsigned long long acc[8][4];
#pragma unroll
    for (int i = 0; i < 8; i++)
#pragma unroll
        for (int j = 0; j < 4; j++) acc[i][j] = 0ull;

    for (int c0 = 0; c0 < CIN; c0 += 16) {
#pragma unroll
        for (int i = t; i < 2048; i += 256) {
            int k = i >> 7, o = i & 127;
            Ws[k][o] = W[o * CIN + c0 + k] * scale_s[o];
        }
#pragma unroll
        for (int i = t; i < 2048; i += 256) {
            int k = i >> 7, n = i & 127;
            Xs[k][n] = Xb[(size_t)(c0 + k) * NPIX + n];
        }
        __syncthreads();

#pragma unroll 4
        for (int k = 0; k < 16; k++) {
            float4 a0 = *(const float4*)&Ws[k][ty * 8];
            float4 a1 = *(const float4*)&Ws[k][ty * 8 + 4];
            unsigned long long ad[8] = {
                pk2(a0.x, a0.x), pk2(a0.y, a0.y), pk2(a0.z, a0.z), pk2(a0.w, a0.w),
                pk2(a1.x, a1.x), pk2(a1.y, a1.y), pk2(a1.z, a1.z), pk2(a1.w, a1.w)};
            unsigned long long bv[4];
#pragma unroll
            for (int j = 0; j < 4; j++)
                bv[j] = *(const unsigned long long*)&Xs[k][tx * 8 + 2 * j];
#pragma unroll
            for (int i = 0; i < 8; i++)
#pragma unroll
                for (int j = 0; j < 4; j++) fma2(acc[i][j], ad[i], bv[j]);
        }
        __syncthreads();
    }

    float* Yb = Y + (size_t)b * yStride + n0 + tx * 8;
#pragma unroll
    for (int i = 0; i < 8; i++) {
        int o = ty * 8 + i;
        float bi = bias_s[o];
        float2 p0 = up2(acc[i][0]), p1 = up2(acc[i][1]);
        float2 p2 = up2(acc[i][2]), p3 = up2(acc[i][3]);
        float4 r0 = make_float4(fmaxf(p0.x + bi, 0.f), fmaxf(p0.y + bi, 0.f),
                                fmaxf(p1.x + bi, 0.f), fmaxf(p1.y + bi, 0.f));
        float4 r1 = make_float4(fmaxf(p2.x + bi, 0.f), fmaxf(p2.y + bi, 0.f),
                                fmaxf(p3.x + bi, 0.f), fmaxf(p3.y + bi, 0.f));
        *(float4*)&Yb[(size_t)o * NPIX]     = r0;
        *(float4*)&Yb[(size_t)o * NPIX + 4] = r1;
    }
}

// ============================================================================
// conv_kq: z=0 -> K[b][k][n] from x_en ;  z=1 -> QT[b][m][k] from x_de
// ============================================================================
__global__ void __launch_bounds__(256) conv_kq_kernel(
    const float* __restrict__ Xen, const float* __restrict__ Xde,
    const float* __restrict__ W,
    const float* __restrict__ gam, const float* __restrict__ bet,
    const float* __restrict__ mean, const float* __restrict__ var)
{
    __shared__ __align__(16) float Ws[16][32];
    __shared__ __align__(16) float Xs[16][128];
    __shared__ float scale_s[32], bias_s[32];

    const int t  = threadIdx.x;
    const int b  = blockIdx.y;
    const int n0 = blockIdx.x * 128;
    const float* X = (blockIdx.z == 0) ? Xen : Xde;

    if (t < 32) {
        float s = gam[t] * rsqrtf(var[t] + BN_EPS);
        scale_s[t] = s;
        bias_s[t]  = bet[t] - mean[t] * s;
    }
    __syncthreads();

    const float* Xb = X + (size_t)b * CC * NPIX + n0;
    const int ty = t >> 4, tx = t & 15;

    unsigned long long acc[2][4];
#pragma unroll
    for (int i = 0; i < 2; i++)
#pragma unroll
        for (int j = 0; j < 4; j++) acc[i][j] = 0ull;

    for (int c0 = 0; c0 < CC; c0 += 16) {
#pragma unroll
        for (int i = t; i < 512; i += 256) {
            int k = i >> 5, o = i & 31;
            Ws[k][o] = W[o * CC + c0 + k] * scale_s[o];
        }
#pragma unroll
        for (int i = t; i < 2048; i += 256) {
            int k = i >> 7, n = i & 127;
            Xs[k][n] = Xb[(size_t)(c0 + k) * NPIX + n];
        }
        __syncthreads();

#pragma unroll 4
        for (int k = 0; k < 16; k++) {
            float2 a = *(const float2*)&Ws[k][ty * 2];
            unsigned long long a0 = pk2(a.x, a.x);
            unsigned long long a1 = pk2(a.y, a.y);
            unsigned long long bv[4];
#pragma unroll
            for (int j = 0; j < 4; j++)
                bv[j] = *(const unsigned long long*)&Xs[k][tx * 8 + 2 * j];
#pragma unroll
            for (int j = 0; j < 4; j++) { fma2(acc[0][j], a0, bv[j]); fma2(acc[1][j], a1, bv[j]); }
        }
        __syncthreads();
    }

#pragma unroll
    for (int i = 0; i < 2; i++) {
        int o = ty * 2 + i;
        float bi = bias_s[o];
        float v[8];
#pragma unroll
        for (int j = 0; j < 4; j++) {
            float2 p = up2(acc[i][j]);
            v[2 * j]     = fmaxf(p.x + bi, 0.f);
            v[2 * j + 1] = fmaxf(p.y + bi, 0.f);
        }
        if (blockIdx.z == 0) {
            float* Yb = g_K + (size_t)b * C4C * NPIX + n0 + tx * 8;
            *(float4*)&Yb[(size_t)o * NPIX]     = make_float4(v[0], v[1], v[2], v[3]);
            *(float4*)&Yb[(size_t)o * NPIX + 4] = make_float4(v[4], v[5], v[6], v[7]);
        } else {
            float* Yb = g_QT + (size_t)b * NPIX * C4C;
#pragma unroll
            for (int j = 0; j < 8; j++)
                Yb[(size_t)(n0 + tx * 8 + j) * C4C + o] = v[j];
        }
    }
}

// ============================================================================
// norm: M'[b] = max_n ||K[b,:,n]|| * max_m ||Q[b,:,m]||  (Cauchy-Schwarz bound)
// grid = B, 256 threads.
// ============================================================================
__global__ void __launch_bounds__(256) norm_kernel()
{
    __shared__ float r1[256], r2[256];
    const int b = blockIdx.x, t = threadIdx.x;
    const float* Kb  = g_K  + (size_t)b * C4C * NPIX;
    const float* QTb = g_QT + (size_t)b * NPIX * C4C;

    float mk = 0.f, mq = 0.f;
    for (int n = t; n < NPIX; n += 256) {
        float s = 0.f;
#pragma unroll
        for (int k = 0; k < C4C; k++) {
            float v = Kb[(size_t)k * NPIX + n];
            s += v * v;
        }
        mk = fmaxf(mk, s);
        const float4* qr = (const float4*)(QTb + (size_t)n * C4C);
        float s2 = 0.f;
#pragma unroll
        for (int j = 0; j < 8; j++) {
            float4 q = qr[j];
            s2 += q.x * q.x + q.y * q.y + q.z * q.z + q.w * q.w;
        }
        mq = fmaxf(mq, s2);
    }
    r1[t] = mk; r2[t] = mq;
    __syncthreads();
    for (int s = 128; s > 0; s >>= 1) {
        if (t < s) { r1[t] = fmaxf(r1[t], r1[t + s]); r2[t] = fmaxf(r2[t], r2[t + s]); }
        __syncthreads();
    }
    if (t == 0) g_M[b] = sqrtf(r1[0]) * sqrtf(r2[0]);
}

// ============================================================================
// fused_attn: per (n-tile 128, b):
//   loop m-chunks of 64:
//     GEMM1: P(64m x 128n) = QT(64m x 32k) x K(32k x 128n)   [tf32 mma]
//     exp(P - M') in regs, accumulate Z partial
//     GEMM2: feat(128c x 128n) += V(128c x 64m) x P(64m x 128n) [tf32 mma]
//   write unnormalized feat; scale kernel divides by Z.
// No KQ materialization.  grid (NT, B), 256 threads.
// ============================================================================
#define CH   64
#define NCH  36
// smem float offsets
#define OFF_K   0
#define SZ_K    (32 * 136)              // 4352
#define OFF_QT  4352
#define SZ_QT   (64 * 36)               // 2304 (x2 bufs)
#define OFF_V   (4352 + 2 * 2304)       // 8960
#define SZ_V    (128 * 68)              // 8704 (x2 bufs)
#define OFF_P   (8960 + 2 * 8704)       // 26368
#define SZ_P    (64 * 136)              // 8704
#define FA_SMEM_FLOATS (26368 + 8704)   // 35072
#define FA_SMEM_BYTES  (FA_SMEM_FLOATS * 4)

__global__ void __launch_bounds__(256, 1) fused_attn_kernel(float* __restrict__ out)
{
    extern __shared__ __align__(16) float fs[];
    __shared__ float zred[256];

    const int t  = threadIdx.x;
    const int b  = blockIdx.y;
    const int n0 = blockIdx.x * 128;
    const int lane = t & 31, wid = t >> 5;
    const int g = lane >> 2, c4 = lane & 3;
    const int wr = wid >> 2;     // GEMM1 m-half / GEMM2 c-half  (0..1)
    const int wn = wid & 3;      // n-quarter (0..3)
    const float Mb = g_M[b];

    float* Ksm = fs + OFF_K;
    float* Psm = fs + OFF_P;

    const float* Kg  = g_K  + (size_t)b * C4C * NPIX;
    const float* QTg = g_QT + (size_t)b * NPIX * C4C;
    const float* Vg  = g_V  + (size_t)b * CC * NPIX;

    const uint32_t sb = smem_to_u32(fs);

    // prologue: K tile (32k x 128n) -> Ksm, 4 cp16 per thread
    {
        int k = t >> 3, seg = t & 7;    // seg: 16 floats
        uint32_t dst = sb + (uint32_t)(OFF_K + k * 136 + seg * 16) * 4;
        const float* src = Kg + (size_t)k * NPIX + n0 + seg * 16;
        cp16(dst,      src);
        cp16(dst + 16, src + 4);
        cp16(dst + 32, src + 8);
        cp16(dst + 48, src + 12);
    }

    // chunk loader: QT rows [m0..m0+64) and V cols [m0..m0+64)
    auto load_chunk = [&](int m0, int bufsel) {
        int r = t >> 2, sg = t & 3;     // QT: 64 rows x 4 segs of 8 floats
        uint32_t qdst = sb + (uint32_t)(OFF_QT + bufsel * SZ_QT + r * 36 + sg * 8) * 4;
        const float* qsrc = QTg + (size_t)(m0 + r) * C4C + sg * 8;
        cp16(qdst,      qsrc);
        cp16(qdst + 16, qsrc + 4);
        int c = t >> 1, hf = t & 1;     // V: 128 rows x 2 halves of 32 floats
        uint32_t vdst = sb + (uint32_t)(OFF_V + bufsel * SZ_V + c * 68 + hf * 32) * 4;
        const float* vsrc = Vg + (size_t)c * NPIX + m0 + hf * 32;
#pragma unroll
        for (int j = 0; j < 8; j++) cp16(vdst + j * 16, vsrc + j * 4);
    };

    load_chunk(0, 0);
    CP_COMMIT();

    float acc[4][4][4];
#pragma unroll
    for (int ct = 0; ct < 4; ct++)
#pragma unroll
        for (int nt = 0; nt < 4; nt++)
#pragma unroll
            for (int j = 0; j < 4; j++) acc[ct][nt][j] = 0.f;
    float zacc = 0.f;

    for (int i = 0; i < NCH; i++) {
        const int buf = i & 1;
        CP_WAIT0();
        __syncthreads();                        // chunk ready; prev GEMM2 done
        if (i < NCH - 1) { load_chunk((i + 1) * CH, buf ^ 1); CP_COMMIT(); }

        const float* QTs = fs + OFF_QT + buf * SZ_QT;
        const float* Vs  = fs + OFF_V  + buf * SZ_V;

        // ---- GEMM1: P(64m x 128n), warp tile 32m x 32n ----
        float pf[2][4][4];
#pragma unroll
        for (int mt = 0; mt < 2; mt++)
#pragma unroll
            for (int nt = 0; nt < 4; nt++)
#pragma unroll
                for (int j = 0; j < 4; j++) pf[mt][nt][j] = 0.f;

#pragma unroll
        for (int ks = 0; ks < 4; ks++) {
            uint32_t a[2][4];
#pragma unroll
            for (int mt = 0; mt < 2; mt++) {
                int r0 = wr * 32 + mt * 16 + g;
                a[mt][0] = __float_as_uint(QTs[r0 * 36 + ks * 8 + c4]);
                a[mt][1] = __float_as_uint(QTs[(r0 + 8) * 36 + ks * 8 + c4]);
                a[mt][2] = __float_as_uint(QTs[r0 * 36 + ks * 8 + 4 + c4]);
                a[mt][3] = __float_as_uint(QTs[(r0 + 8) * 36 + ks * 8 + 4 + c4]);
            }
            uint32_t bf[4][2];
#pragma unroll
            for (int nt = 0; nt < 4; nt++) {
                int col = wn * 32 + nt * 8 + g;
                bf[nt][0] = __float_as_uint(Ksm[(ks * 8 + c4) * 136 + col]);
                bf[nt][1] = __float_as_uint(Ksm[(ks * 8 + 4 + c4) * 136 + col]);
            }
#pragma unroll
            for (int mt = 0; mt < 2; mt++)
#pragma unroll
                for (int nt = 0; nt < 4; nt++)
                    mma16n8k8(pf[mt][nt], a[mt], bf[nt]);
        }

        // ---- exp + Z, store P to smem ----
#pragma unroll
        for (int mt = 0; mt < 2; mt++)
#pragma unroll
            for (int nt = 0; nt < 4; nt++) {
#pragma unroll
                for (int j = 0; j < 4; j++) {
                    float p = __expf(pf[mt][nt][j] - Mb);
                    zacc += p;
                    pf[mt][nt][j] = p;
                }
                int m = wr * 32 + mt * 16 + g;
                int n = wn * 32 + nt * 8 + 2 * c4;
                *(float2*)&Psm[m * 136 + n] =
                    make_float2(pf[mt][nt][0], pf[mt][nt][1]);
                *(float2*)&Psm[(m + 8) * 136 + n] =
                    make_float2(pf[mt][nt][2], pf[mt][nt][3]);
            }
        __syncthreads();                        // Psm complete

        // ---- GEMM2: feat(128c x 128n) += V(128c x 64m) x P ----
#pragma unroll
        for (int ks = 0; ks < 8; ks++) {
            uint32_t a[4][4];
#pragma unroll
            for (int ct = 0; ct < 4; ct++) {
                int r0 = wr * 64 + ct * 16 + g;
                a[ct][0] = __float_as_uint(Vs[r0 * 68 + ks * 8 + c4]);
                a[ct][1] = __float_as_uint(Vs[(r0 + 8) * 68 + ks * 8 + c4]);
                a[ct][2] = __float_as_uint(Vs[r0 * 68 + ks * 8 + 4 + c4]);
                a[ct][3] = __float_as_uint(Vs[(r0 + 8) * 68 + ks * 8 + 4 + c4]);
            }
            uint32_t bf2[4][2];
#pragma unroll
            for (int nt = 0; nt < 4; nt++) {
                int col = wn * 32 + nt * 8 + g;
                bf2[nt][0] = __float_as_uint(Psm[(ks * 8 + c4) * 136 + col]);
                bf2[nt][1] = __float_as_uint(Psm[(ks * 8 + 4 + c4) * 136 + col]);
            }
#pragma unroll
            for (int ct = 0; ct < 4; ct++)
#pragma unroll
                for (int nt = 0; nt < 4; nt++)
                    mma16n8k8(acc[ct][nt], a[ct], bf2[nt]);
        }
    }

    // Z partial
    zred[t] = zacc;
    __syncthreads();
    for (int s = 128; s > 0; s >>= 1) {
        if (t < s) zred[t] += zred[t + s];
        __syncthreads();
    }
    if (t == 0) g_pZ[b * NT + blockIdx.x] = zred[0];

    // store unnormalized feat (32B-sector-aligned v2 stores)
    float* Ob = out + (size_t)b * (2 * CC) * NPIX + (size_t)CC * NPIX + n0;
#pragma unroll
    for (int ct = 0; ct < 4; ct++) {
        int c = wr * 64 + ct * 16 + g;
#pragma unroll
        for (int nt = 0; nt < 4; nt++) {
            int n = wn * 32 + nt * 8 + 2 * c4;
            *(float2*)&Ob[(size_t)c * NPIX + n] =
                make_float2(acc[ct][nt][0], acc[ct][nt][1]);
            *(float2*)&Ob[(size_t)(c + 8) * NPIX + n] =
                make_float2(acc[ct][nt][2], acc[ct][nt][3]);
        }
    }
}

// ============================================================================
// scale: Z[b] = sum of NT partials; feat half *= 1/Z.  grid (NT, B).
// ============================================================================
__global__ void __launch_bounds__(256) scale_kernel(float* __restrict__ out)
{
    __shared__ float zinv;
    const int t  = threadIdx.x;
    const int b  = blockIdx.y;
    const int n0 = blockIdx.x * 128;
    if (t == 0) {
        float z = 0.f;
#pragma unroll
        for (int j = 0; j < NT; j++) z += g_pZ[b * NT + j];
        zinv = 1.f / z;
    }
    __syncthreads();
    const float inv = zinv;

    const int c = t >> 1, h = t & 1;
    float* O = out + (size_t)b * (2 * CC) * NPIX + (size_t)(CC + c) * NPIX
                   + n0 + h * 64;
#pragma unroll
    for (int q = 0; q < 16; q++) {
        float4 v = *(float4*)&O[q * 4];
        v.x *= inv; v.y *= inv; v.z *= inv; v.w *= inv;
        *(float4*)&O[q * 4] = v;
    }
}

// ============================================================================
// launch
// ============================================================================
extern "C" void kernel_launch(void* const* d_in, const int* in_sizes, int n_in,
                              void* d_out, int out_size)
{
    const float* x_en   = (const float*)d_in[0];
    const float* x_de   = (const float*)d_in[1];
    const float* x_cat  = (const float*)d_in[2];
    const float* w_kq   = (const float*)d_in[3];
    const float* kq_g   = (const float*)d_in[4];
    const float* kq_b   = (const float*)d_in[5];
    const float* kq_m   = (const float*)d_in[6];
    const float* kq_v   = (const float*)d_in[7];
    const float* w_v    = (const float*)d_in[8];
    const float* v_g    = (const float*)d_in[9];
    const float* v_b    = (const float*)d_in[10];
    const float* v_m    = (const float*)d_in[11];
    const float* v_v    = (const float*)d_in[12];
    const float* w_red  = (const float*)d_in[13];
    const float* red_g  = (const float*)d_in[14];
    const float* red_b  = (const float*)d_in[15];
    const float* red_m  = (const float*)d_in[16];
    const float* red_v  = (const float*)d_in[17];
    float* out = (float*)d_out;

    float* pV = nullptr;
    cudaGetSymbolAddress((void**)&pV, g_V);

    cudaFuncSetAttribute(fused_attn_kernel,
                         cudaFuncAttributeMaxDynamicSharedMemorySize, FA_SMEM_BYTES);

    const size_t twoCN = (size_t)2 * CC * NPIX;
    const size_t CN    = (size_t)CC * NPIX;

    // K, QT
    conv_kq_kernel<<<dim3(NT, BB, 2), 256>>>(x_en, x_de, w_kq,
                                             kq_g, kq_b, kq_m, kq_v);
    // M' upper bound per batch
    norm_kernel<<<BB, 256>>>();
    // x = relu(BN(w_red @ x_cat)) -> output channels [0, C)
    conv128_kernel<<<dim3(NT, BB), 256>>>(x_cat, twoCN, 2 * CC, w_red,
                                          red_g, red_b, red_m, red_v,
                                          out, twoCN);
    // V = relu(BN(w_v @ x))
    conv128_kernel<<<dim3(NT, BB), 256>>>(out, twoCN, CC, w_v,
                                          v_g, v_b, v_m, v_v,
                                          pV, CN);
    // fused attention (no KQ materialization) + Z partials
    fused_attn_kernel<<<dim3(NT, BB), 256, FA_SMEM_BYTES>>>(out);
    // normalize feat half by 1/Z
    scale_kernel<<<dim3(NT, BB), 256>>>(out);
}